// round 11
// baseline (speedup 1.0000x reference)
#include <cuda_runtime.h>

#define Bb 4
#define Cc 64
#define Hh 256
#define Ww 256
#define Nn (Hh*Ww)
#define NWORDS (Nn/4)          // 16384 packed words per image
#define NG (Ww/4)              // 64 words per row
#define NPAIRS 12
#define HALF_S 512
#define MAXS 1024
#define NFEAT (NPAIRS*Cc*MAXS)

__device__ unsigned char g_pred[Bb*Nn];   // packed argmax bytes (4 px/word)
__device__ int g_idx[NPAIRS*MAXS];

// ---------------- argmax over 4 planes, 4 px/thread, pure stream -------------
__global__ void k_argmax(const float* __restrict__ preds) {
    int gt = blockIdx.x * blockDim.x + threadIdx.x;   // over Bb*NWORDS
    if (gt >= Bb*NWORDS) return;
    int b = gt >> 14;
    int w = gt & (NWORDS-1);
    const float* pb = preds + (size_t)b * 4 * Nn;
    float4 v0 = ((const float4*)pb)[w];
    float4 v1 = ((const float4*)(pb + Nn))[w];
    float4 v2 = ((const float4*)(pb + 2*Nn))[w];
    float4 v3 = ((const float4*)(pb + 3*Nn))[w];
    unsigned packed = 0;
    {   float a=v0.x; int bi=0;
        if (v1.x>a){a=v1.x;bi=1;} if (v2.x>a){a=v2.x;bi=2;} if (v3.x>a){a=v3.x;bi=3;}
        packed |= (unsigned)bi; }
    {   float a=v0.y; int bi=0;
        if (v1.y>a){a=v1.y;bi=1;} if (v2.y>a){a=v2.y;bi=2;} if (v3.y>a){a=v3.y;bi=3;}
        packed |= (unsigned)bi << 8; }
    {   float a=v0.z; int bi=0;
        if (v1.z>a){a=v1.z;bi=1;} if (v2.z>a){a=v2.z;bi=2;} if (v3.z>a){a=v3.z;bi=3;}
        packed |= (unsigned)bi << 16; }
    {   float a=v0.w; int bi=0;
        if (v1.w>a){a=v1.w;bi=1;} if (v2.w>a){a=v2.w;bi=2;} if (v3.w>a){a=v3.w;bi=3;}
        packed |= (unsigned)bi << 24; }
    ((unsigned*)g_pred)[gt] = packed;
}

// -------- select with inline dilate: one block per (b,cls) pair --------------
// Each thread owns 16 consecutive words (1/4 row, same y). Dilate from g_pred
// rows y-1..y+1 (L2-hot), merge labels, then rank-compact:
//   hard rank r -> slot r (r<1024); easy rank e -> slot 512+max(totH-512,0)+e
__global__ void __launch_bounds__(1024)
k_select(const int* __restrict__ labels, float* __restrict__ out) {
    int pair = blockIdx.x;
    int b = pair / 3;
    int cls = pair % 3 + 1;
    int tid = threadIdx.x;
    g_idx[pair*MAXS + tid] = -1;
    if (tid == 0) out[NFEAT + pair] = (float)cls;

    const unsigned* pw = (const unsigned*)g_pred + b*NWORDS;
    int w0  = tid * 16;          // first word index
    int y   = w0 >> 6;           // row (tid/4)
    int cg0 = w0 & (NG-1);       // 0,16,32,48

    // load 3 row windows of 16 words each
    unsigned cur[16], up[16], dn[16];
    {
        const uint4* rc = (const uint4*)(pw + y*NG + cg0);
#pragma unroll
        for (int j = 0; j < 4; j++) {
            uint4 q = rc[j];
            cur[j*4]=q.x; cur[j*4+1]=q.y; cur[j*4+2]=q.z; cur[j*4+3]=q.w;
        }
    }
    if (y > 0) {
        const uint4* ru = (const uint4*)(pw + (y-1)*NG + cg0);
#pragma unroll
        for (int j = 0; j < 4; j++) {
            uint4 q = ru[j];
            up[j*4]=q.x; up[j*4+1]=q.y; up[j*4+2]=q.z; up[j*4+3]=q.w;
        }
    } else {
#pragma unroll
        for (int j = 0; j < 16; j++) up[j] = 0;
    }
    if (y < Hh-1) {
        const uint4* rd = (const uint4*)(pw + (y+1)*NG + cg0);
#pragma unroll
        for (int j = 0; j < 4; j++) {
            uint4 q = rd[j];
            dn[j*4]=q.x; dn[j*4+1]=q.y; dn[j*4+2]=q.z; dn[j*4+3]=q.w;
        }
    } else {
#pragma unroll
        for (int j = 0; j < 16; j++) dn[j] = 0;
    }

    // boundary bytes (0 is neutral: classes >= 0 and center is included in max)
    unsigned lbC = (cg0 > 0) ? (pw[y*NG + cg0 - 1] >> 24) : 0u;
    unsigned lbU = (cg0 > 0 && y > 0)    ? (pw[(y-1)*NG + cg0 - 1] >> 24) : 0u;
    unsigned lbD = (cg0 > 0 && y < Hh-1) ? (pw[(y+1)*NG + cg0 - 1] >> 24) : 0u;
    unsigned rbC = (cg0 < NG-16) ? (pw[y*NG + cg0 + 16] & 0xffu) : 0u;
    unsigned rbU = (cg0 < NG-16 && y > 0)    ? (pw[(y-1)*NG + cg0 + 16] & 0xffu) : 0u;
    unsigned rbD = (cg0 < NG-16 && y < Hh-1) ? (pw[(y+1)*NG + cg0 + 16] & 0xffu) : 0u;

    // dilate + merge labels -> code words
    unsigned w[16];
#pragma unroll
    for (int i = 0; i < 16; i++) {
        unsigned lc = (i > 0)  ? (cur[i-1] >> 24) : lbC;
        unsigned lu = (i > 0)  ? (up[i-1]  >> 24) : lbU;
        unsigned ld = (i > 0)  ? (dn[i-1]  >> 24) : lbD;
        unsigned rc = (i < 15) ? (cur[i+1] & 0xffu) : rbC;
        unsigned ru = (i < 15) ? (up[i+1]  & 0xffu) : rbU;
        unsigned rd = (i < 15) ? (dn[i+1]  & 0xffu) : rbD;
        unsigned m;
        {   unsigned wd = cur[i];
            m = __vmaxu4(wd, __vmaxu4((wd << 8) | lc, (wd >> 8) | (rc << 24))); }
        {   unsigned wd = up[i];
            m = __vmaxu4(m, __vmaxu4(wd, __vmaxu4((wd << 8) | lu, (wd >> 8) | (ru << 24)))); }
        {   unsigned wd = dn[i];
            m = __vmaxu4(m, __vmaxu4(wd, __vmaxu4((wd << 8) | ld, (wd >> 8) | (rd << 24)))); }
        int4 l = ((const int4*)(labels + (size_t)b*Nn))[w0 + i];
        unsigned lab4 = (unsigned)l.x | ((unsigned)l.y << 8) |
                        ((unsigned)l.z << 16) | ((unsigned)l.w << 24);
        w[i] = lab4 | (m << 4);
    }

    const unsigned clsL = (unsigned)cls * 0x01010101u;
    const unsigned clsH = (unsigned)cls * 0x10101010u;

    int hbits = 0, ebits = 0;
#pragma unroll
    for (int i = 0; i < 16; i++) {
        unsigned labm = __vcmpeq4(w[i] & 0x0F0F0F0Fu, clsL);
        unsigned pdm  = __vcmpeq4(w[i] & 0xF0F0F0F0u, clsH);
        ebits += __popc(labm & pdm);
        hbits += __popc(labm & ~pdm);
    }
    unsigned long long v = ((unsigned long long)(hbits>>3) << 32) | (unsigned)(ebits>>3);
    unsigned long long own = v;
    int lane = tid & 31, wid = tid >> 5;
#pragma unroll
    for (int o = 1; o < 32; o <<= 1) {
        unsigned long long n = __shfl_up_sync(0xffffffffu, v, o);
        if (lane >= o) v += n;
    }
    __shared__ unsigned long long wsum[32];
    __shared__ unsigned long long s_total;
    if (lane == 31) wsum[wid] = v;
    __syncthreads();
    if (wid == 0) {
        unsigned long long ww = wsum[lane];
#pragma unroll
        for (int o = 1; o < 32; o <<= 1) {
            unsigned long long n = __shfl_up_sync(0xffffffffu, ww, o);
            if (lane >= o) ww += n;
        }
        wsum[lane] = ww;
        if (lane == 31) s_total = ww;
    }
    __syncthreads();

    unsigned long long excl = v - own + (wid > 0 ? wsum[wid-1] : 0ULL);
    int hr = (int)(excl >> 32);
    int er = (int)(excl & 0xffffffffULL);
    int totH = (int)(s_total >> 32);
    int excess = totH > HALF_S ? totH - HALF_S : 0;

    int base = tid * 64;
    int* slots = g_idx + pair*MAXS;
#pragma unroll
    for (int i = 0; i < 16; i++) {
        unsigned labm = __vcmpeq4(w[i] & 0x0F0F0F0Fu, clsL);
        if (!labm) continue;
        unsigned pdm = __vcmpeq4(w[i] & 0xF0F0F0F0u, clsH);
#pragma unroll
        for (int k = 0; k < 4; k++) {
            if ((labm >> (k*8)) & 0xffu) {
                int p = base + i*4 + k;
                if ((pdm >> (k*8)) & 0xffu) {
                    int slot = HALF_S + excess + er;
                    if (slot < MAXS) slots[slot] = p;
                    er++;
                } else {
                    if (hr < MAXS) slots[hr] = p;
                    hr++;
                }
            }
        }
    }
}

// ------------- gather: 8 samples per thread (2 channels x 4 slots) ----------
__global__ void k_gather(const float* __restrict__ feat, float* __restrict__ out) {
    int t = blockIdx.x * blockDim.x + threadIdx.x;   // over NFEAT/8
    if (t >= NFEAT/8) return;
    int s4   = t & 255;              // sample quad
    int c    = (t >> 8) & 31;        // channel (low half)
    int pair = t >> 13;
    int b = pair / 3;
    const int* slots = g_idx + pair*MAXS + s4*4;
    int p0 = slots[0], p1 = slots[1], p2 = slots[2], p3 = slots[3];
    const float* planeA = feat + ((size_t)(b*Cc + c)) * Nn;
    const float* planeB = planeA + (size_t)32 * Nn;
    float4 ra, rb;
    ra.x = (p0 >= 0) ? __ldg(planeA + p0) : 0.0f;
    ra.y = (p1 >= 0) ? __ldg(planeA + p1) : 0.0f;
    ra.z = (p2 >= 0) ? __ldg(planeA + p2) : 0.0f;
    ra.w = (p3 >= 0) ? __ldg(planeA + p3) : 0.0f;
    rb.x = (p0 >= 0) ? __ldg(planeB + p0) : 0.0f;
    rb.y = (p1 >= 0) ? __ldg(planeB + p1) : 0.0f;
    rb.z = (p2 >= 0) ? __ldg(planeB + p2) : 0.0f;
    rb.w = (p3 >= 0) ? __ldg(planeB + p3) : 0.0f;
    int o4 = pair*16384 + c*256 + s4;        // float4 index within out
    ((float4*)out)[o4]          = ra;
    ((float4*)out)[o4 + 32*256] = rb;
}

extern "C" void kernel_launch(void* const* d_in, const int* in_sizes, int n_in,
                              void* d_out, int out_size) {
    const float* feat   = (const float*)d_in[0];  // [4,64,256,256]
    const int*   labels = (const int*)d_in[1];    // [4,256,256]
    const float* preds  = (const float*)d_in[2];  // [4,4,256,256]
    float* out = (float*)d_out;

    k_argmax<<<(Bb*NWORDS + 255) / 256, 256>>>(preds);
    k_select<<<NPAIRS, 1024>>>(labels, out);
    k_gather<<<(NFEAT/8 + 255) / 256, 256>>>(feat, out);
}

// round 12
// speedup vs baseline: 1.0738x; 1.0738x over previous
#include <cuda_runtime.h>

#define Bb 4
#define Cc 64
#define Hh 256
#define Ww 256
#define Nn (Hh*Ww)
#define NPAIRS 12
#define HALF_S 512
#define MAXS 1024
#define NFEAT (NPAIRS*Cc*MAXS)

#define TILE_R 2          // interior rows per block
#define NG (Ww/4)         // 64 column groups of 4
#define PREP_T 256        // threads per prep block
#define ROWS_BLK (Hh/TILE_R)   // 128 row-blocks per image

__device__ unsigned char g_code[Bb*Nn];   // per pixel: lab | (pd<<4)
__device__ int g_idx[NPAIRS*MAXS];

// ------- fused: argmax (vec4) -> 3x3 max-dilate (SIMD bytes) -> pack ---------
__global__ void __launch_bounds__(PREP_T)
k_prep(const float* __restrict__ preds, const int* __restrict__ labels) {
    // grid: Bb * ROWS_BLK = 512 blocks, 256 threads
    int blk = blockIdx.x;
    int b = blk >> 7;                        // / ROWS_BLK
    int ty0 = (blk & (ROWS_BLK-1)) * TILE_R; // first interior row
    int tid = threadIdx.x;

    __shared__ unsigned spred[TILE_R+2][NG]; // packed argmax bytes

    const float* pb = preds + (size_t)b * 4 * Nn;

    // pass 1: argmax for rows ty0-1..ty0+TILE_R ((TILE_R+2)*64 = 256 tasks, 1/thread)
    {
        int r = tid >> 6;            // 0..3
        int cg = tid & (NG-1);       // 0..63
        int y = ty0 - 1 + r;
        unsigned packed = 0;
        if (y >= 0 && y < Hh) {
            int off4 = (y*Ww) / 4 + cg;
            float4 v0 = ((const float4*)pb)[off4];
            float4 v1 = ((const float4*)(pb + Nn))[off4];
            float4 v2 = ((const float4*)(pb + 2*Nn))[off4];
            float4 v3 = ((const float4*)(pb + 3*Nn))[off4];
            {   float a=v0.x; int bi=0;
                if (v1.x>a){a=v1.x;bi=1;} if (v2.x>a){a=v2.x;bi=2;} if (v3.x>a){a=v3.x;bi=3;}
                packed |= (unsigned)bi; }
            {   float a=v0.y; int bi=0;
                if (v1.y>a){a=v1.y;bi=1;} if (v2.y>a){a=v2.y;bi=2;} if (v3.y>a){a=v3.y;bi=3;}
                packed |= (unsigned)bi << 8; }
            {   float a=v0.z; int bi=0;
                if (v1.z>a){a=v1.z;bi=1;} if (v2.z>a){a=v2.z;bi=2;} if (v3.z>a){a=v3.z;bi=3;}
                packed |= (unsigned)bi << 16; }
            {   float a=v0.w; int bi=0;
                if (v1.w>a){a=v1.w;bi=1;} if (v2.w>a){a=v2.w;bi=2;} if (v3.w>a){a=v3.w;bi=3;}
                packed |= (unsigned)bi << 24; }
        }
        spred[r][cg] = packed;
    }
    __syncthreads();

    // pass 2: dilate + pack labels (TILE_R*64 = 128 tasks, threads 0..127)
    if (tid < TILE_R*NG) {
        int r = tid >> 6;
        int cg = tid & (NG-1);
        int rr = r + 1;
        unsigned m = 0;
#pragma unroll
        for (int d = -1; d <= 1; d++) {
            unsigned w = spred[rr+d][cg];
            unsigned lb = (cg > 0)    ? (spred[rr+d][cg-1] >> 24) : 0u;
            unsigned rb = (cg < NG-1) ? (spred[rr+d][cg+1] & 0xffu) : 0u;
            unsigned wl = (w << 8) | lb;
            unsigned wr = (w >> 8) | (rb << 24);
            m = __vmaxu4(m, __vmaxu4(w, __vmaxu4(wl, wr)));
        }
        int y = ty0 + r;
        int off4 = (y*Ww)/4 + cg;
        int4 l = ((const int4*)(labels + (size_t)b*Nn))[off4];
        unsigned lab4 = (unsigned)l.x | ((unsigned)l.y << 8) |
                        ((unsigned)l.z << 16) | ((unsigned)l.w << 24);
        ((unsigned*)(g_code + (size_t)b*Nn))[off4] = lab4 | (m << 4);
    }
}

// ---------------- selection: one block per (b,cls) pair ----------------------
// hard rank r -> slot r (r<1024); easy rank e -> slot 512+max(totH-512,0)+e (<1024)
__global__ void __launch_bounds__(1024)
k_select(float* __restrict__ out) {
    int pair = blockIdx.x;
    int b = pair / 3;
    int cls = pair % 3 + 1;
    int tid = threadIdx.x;
    g_idx[pair*MAXS + tid] = -1;
    if (tid == 0) out[NFEAT + pair] = (float)cls;   // label tail

    const uint4* codes = (const uint4*)(g_code + b*Nn) + tid*4;
    uint4 q0 = codes[0], q1 = codes[1], q2 = codes[2], q3 = codes[3];
    unsigned w[16] = { q0.x,q0.y,q0.z,q0.w, q1.x,q1.y,q1.z,q1.w,
                       q2.x,q2.y,q2.z,q2.w, q3.x,q3.y,q3.z,q3.w };
    const unsigned clsL = (unsigned)cls * 0x01010101u;
    const unsigned clsH = (unsigned)cls * 0x10101010u;

    int hbits = 0, ebits = 0;
#pragma unroll
    for (int i = 0; i < 16; i++) {
        unsigned labm = __vcmpeq4(w[i] & 0x0F0F0F0Fu, clsL);
        unsigned pdm  = __vcmpeq4(w[i] & 0xF0F0F0F0u, clsH);
        ebits += __popc(labm & pdm);
        hbits += __popc(labm & ~pdm);
    }
    unsigned long long v = ((unsigned long long)(hbits>>3) << 32) | (unsigned)(ebits>>3);
    unsigned long long own = v;
    int lane = tid & 31, wid = tid >> 5;
#pragma unroll
    for (int o = 1; o < 32; o <<= 1) {
        unsigned long long n = __shfl_up_sync(0xffffffffu, v, o);
        if (lane >= o) v += n;
    }
    __shared__ unsigned long long wsum[32];
    __shared__ unsigned long long s_total;
    if (lane == 31) wsum[wid] = v;
    __syncthreads();
    if (wid == 0) {
        unsigned long long ww = wsum[lane];
#pragma unroll
        for (int o = 1; o < 32; o <<= 1) {
            unsigned long long n = __shfl_up_sync(0xffffffffu, ww, o);
            if (lane >= o) ww += n;
        }
        wsum[lane] = ww;
        if (lane == 31) s_total = ww;
    }
    __syncthreads();

    unsigned long long excl = v - own + (wid > 0 ? wsum[wid-1] : 0ULL);
    int hr = (int)(excl >> 32);
    int er = (int)(excl & 0xffffffffULL);
    int totH = (int)(s_total >> 32);
    int excess = totH > HALF_S ? totH - HALF_S : 0;

    int base = tid * 64;
    int* slots = g_idx + pair*MAXS;
#pragma unroll
    for (int i = 0; i < 16; i++) {
        unsigned labm = __vcmpeq4(w[i] & 0x0F0F0F0Fu, clsL);
        if (!labm) continue;
        unsigned pdm = __vcmpeq4(w[i] & 0xF0F0F0F0u, clsH);
#pragma unroll
        for (int k = 0; k < 4; k++) {
            if ((labm >> (k*8)) & 0xffu) {
                int p = base + i*4 + k;
                if ((pdm >> (k*8)) & 0xffu) {
                    int slot = HALF_S + excess + er;
                    if (slot < MAXS) slots[slot] = p;
                    er++;
                } else {
                    if (hr < MAXS) slots[hr] = p;
                    hr++;
                }
            }
        }
    }
}

// ------------- gather: 8 samples per thread (2 channels x 4 slots) ----------
__global__ void k_gather(const float* __restrict__ feat, float* __restrict__ out) {
    int t = blockIdx.x * blockDim.x + threadIdx.x;   // over NFEAT/8
    if (t >= NFEAT/8) return;
    int s4   = t & 255;              // sample quad
    int c    = (t >> 8) & 31;        // channel (low half)
    int pair = t >> 13;
    int b = pair / 3;
    const int* slots = g_idx + pair*MAXS + s4*4;
    int p0 = slots[0], p1 = slots[1], p2 = slots[2], p3 = slots[3];
    const float* planeA = feat + ((size_t)(b*Cc + c)) * Nn;
    const float* planeB = planeA + (size_t)32 * Nn;
    float4 ra, rb;
    ra.x = (p0 >= 0) ? __ldg(planeA + p0) : 0.0f;
    ra.y = (p1 >= 0) ? __ldg(planeA + p1) : 0.0f;
    ra.z = (p2 >= 0) ? __ldg(planeA + p2) : 0.0f;
    ra.w = (p3 >= 0) ? __ldg(planeA + p3) : 0.0f;
    rb.x = (p0 >= 0) ? __ldg(planeB + p0) : 0.0f;
    rb.y = (p1 >= 0) ? __ldg(planeB + p1) : 0.0f;
    rb.z = (p2 >= 0) ? __ldg(planeB + p2) : 0.0f;
    rb.w = (p3 >= 0) ? __ldg(planeB + p3) : 0.0f;
    int o4 = pair*16384 + c*256 + s4;        // float4 index within out
    ((float4*)out)[o4]          = ra;
    ((float4*)out)[o4 + 32*256] = rb;
}

extern "C" void kernel_launch(void* const* d_in, const int* in_sizes, int n_in,
                              void* d_out, int out_size) {
    const float* feat   = (const float*)d_in[0];  // [4,64,256,256]
    const int*   labels = (const int*)d_in[1];    // [4,256,256]
    const float* preds  = (const float*)d_in[2];  // [4,4,256,256]
    float* out = (float*)d_out;

    k_prep<<<Bb*ROWS_BLK, PREP_T>>>(preds, labels);
    k_select<<<NPAIRS, 1024>>>(out);
    k_gather<<<(NFEAT/8 + 255) / 256, 256>>>(feat, out);
}

// round 14
// speedup vs baseline: 1.6000x; 1.4901x over previous
#include <cuda_runtime.h>

#define Bb 4
#define Cc 64
#define Hh 256
#define Ww 256
#define Nn (Hh*Ww)
#define NPAIRS 12
#define HALF_S 512
#define MAXS 1024
#define NFEAT (NPAIRS*Cc*MAXS)

#define TILE_R 2          // interior rows per block
#define NG (Ww/4)         // 64 column groups of 4
#define PREP_T 128        // threads per prep block
#define ROWS_BLK (Hh/TILE_R)   // 128 row-blocks per image

__device__ unsigned char g_code[Bb*Nn];   // per pixel: lab | (pd<<4)
__device__ int g_idx[NPAIRS*MAXS];

__device__ __forceinline__ unsigned argmax4(float4 v0, float4 v1, float4 v2, float4 v3) {
    unsigned packed = 0;
    {   float a=v0.x; int bi=0;
        if (v1.x>a){a=v1.x;bi=1;} if (v2.x>a){a=v2.x;bi=2;} if (v3.x>a){a=v3.x;bi=3;}
        packed |= (unsigned)bi; }
    {   float a=v0.y; int bi=0;
        if (v1.y>a){a=v1.y;bi=1;} if (v2.y>a){a=v2.y;bi=2;} if (v3.y>a){a=v3.y;bi=3;}
        packed |= (unsigned)bi << 8; }
    {   float a=v0.z; int bi=0;
        if (v1.z>a){a=v1.z;bi=1;} if (v2.z>a){a=v2.z;bi=2;} if (v3.z>a){a=v3.z;bi=3;}
        packed |= (unsigned)bi << 16; }
    {   float a=v0.w; int bi=0;
        if (v1.w>a){a=v1.w;bi=1;} if (v2.w>a){a=v2.w;bi=2;} if (v3.w>a){a=v3.w;bi=3;}
        packed |= (unsigned)bi << 24; }
    return packed;
}

// ------- fused: argmax (vec4, 2 tasks/thread, loads front-batched) ->
//         3x3 max-dilate (SIMD bytes) -> pack with labels --------------------
__global__ void __launch_bounds__(PREP_T)
k_prep(const float* __restrict__ preds, const int* __restrict__ labels) {
    // grid: Bb * ROWS_BLK = 512 blocks, 128 threads
    int blk = blockIdx.x;
    int b = blk >> 7;                        // / ROWS_BLK
    int ty0 = (blk & (ROWS_BLK-1)) * TILE_R; // first interior row
    int tid = threadIdx.x;

    __shared__ unsigned spred[TILE_R+2][NG]; // packed argmax bytes

    const float* pb = preds + (size_t)b * 4 * Nn;

    // pass 1: 256 tasks, 2 per thread. Front-batch all 8 float4 loads so they
    // are simultaneously in flight (register-level MLP).
    int task0 = tid, task1 = tid + PREP_T;
    int r0 = task0 >> 6, cg0t = task0 & (NG-1);
    int r1 = task1 >> 6, cg1t = task1 & (NG-1);
    int y0 = ty0 - 1 + r0;
    int y1 = ty0 - 1 + r1;
    bool ok0 = (y0 >= 0 && y0 < Hh);
    bool ok1 = (y1 >= 0 && y1 < Hh);
    int off0 = (y0*Ww)/4 + cg0t;
    int off1 = (y1*Ww)/4 + cg1t;

    float4 a0, a1, a2, a3, b0, b1, b2, b3;
    if (ok0) {
        a0 = ((const float4*)pb)[off0];
        a1 = ((const float4*)(pb + Nn))[off0];
        a2 = ((const float4*)(pb + 2*Nn))[off0];
        a3 = ((const float4*)(pb + 3*Nn))[off0];
    }
    if (ok1) {
        b0 = ((const float4*)pb)[off1];
        b1 = ((const float4*)(pb + Nn))[off1];
        b2 = ((const float4*)(pb + 2*Nn))[off1];
        b3 = ((const float4*)(pb + 3*Nn))[off1];
    }
    spred[r0][cg0t] = ok0 ? argmax4(a0, a1, a2, a3) : 0u;
    spred[r1][cg1t] = ok1 ? argmax4(b0, b1, b2, b3) : 0u;
    __syncthreads();

    // pass 2: dilate + pack labels (TILE_R*64 = 128 tasks, 1 per thread)
    {
        int r = tid >> 6;
        int cg = tid & (NG-1);
        int rr = r + 1;
        unsigned m = 0;
#pragma unroll
        for (int d = -1; d <= 1; d++) {
            unsigned w = spred[rr+d][cg];
            unsigned lb = (cg > 0)    ? (spred[rr+d][cg-1] >> 24) : 0u;
            unsigned rb = (cg < NG-1) ? (spred[rr+d][cg+1] & 0xffu) : 0u;
            unsigned wl = (w << 8) | lb;
            unsigned wr = (w >> 8) | (rb << 24);
            m = __vmaxu4(m, __vmaxu4(w, __vmaxu4(wl, wr)));
        }
        int y = ty0 + r;
        int off4 = (y*Ww)/4 + cg;
        int4 l = ((const int4*)(labels + (size_t)b*Nn))[off4];
        unsigned lab4 = (unsigned)l.x | ((unsigned)l.y << 8) |
                        ((unsigned)l.z << 16) | ((unsigned)l.w << 24);
        ((unsigned*)(g_code + (size_t)b*Nn))[off4] = lab4 | (m << 4);
    }
}

// ---------------- selection: one block per (b,cls) pair ----------------------
// hard rank r -> slot r (r<1024); easy rank e -> slot 512+max(totH-512,0)+e (<1024)
__global__ void __launch_bounds__(1024)
k_select(float* __restrict__ out) {
    int pair = blockIdx.x;
    int b = pair / 3;
    int cls = pair % 3 + 1;
    int tid = threadIdx.x;
    g_idx[pair*MAXS + tid] = -1;
    if (tid == 0) out[NFEAT + pair] = (float)cls;   // label tail

    const uint4* codes = (const uint4*)(g_code + b*Nn) + tid*4;
    uint4 q0 = codes[0], q1 = codes[1], q2 = codes[2], q3 = codes[3];
    unsigned w[16] = { q0.x,q0.y,q0.z,q0.w, q1.x,q1.y,q1.z,q1.w,
                       q2.x,q2.y,q2.z,q2.w, q3.x,q3.y,q3.z,q3.w };
    const unsigned clsL = (unsigned)cls * 0x01010101u;
    const unsigned clsH = (unsigned)cls * 0x10101010u;

    int hbits = 0, ebits = 0;
#pragma unroll
    for (int i = 0; i < 16; i++) {
        unsigned labm = __vcmpeq4(w[i] & 0x0F0F0F0Fu, clsL);
        unsigned pdm  = __vcmpeq4(w[i] & 0xF0F0F0F0u, clsH);
        ebits += __popc(labm & pdm);
        hbits += __popc(labm & ~pdm);
    }
    unsigned long long v = ((unsigned long long)(hbits>>3) << 32) | (unsigned)(ebits>>3);
    unsigned long long own = v;
    int lane = tid & 31, wid = tid >> 5;
#pragma unroll
    for (int o = 1; o < 32; o <<= 1) {
        unsigned long long n = __shfl_up_sync(0xffffffffu, v, o);
        if (lane >= o) v += n;
    }
    __shared__ unsigned long long wsum[32];
    __shared__ unsigned long long s_total;
    if (lane == 31) wsum[wid] = v;
    __syncthreads();
    if (wid == 0) {
        unsigned long long ww = wsum[lane];
#pragma unroll
        for (int o = 1; o < 32; o <<= 1) {
            unsigned long long n = __shfl_up_sync(0xffffffffu, ww, o);
            if (lane >= o) ww += n;
        }
        wsum[lane] = ww;
        if (lane == 31) s_total = ww;
    }
    __syncthreads();

    unsigned long long excl = v - own + (wid > 0 ? wsum[wid-1] : 0ULL);
    int hr = (int)(excl >> 32);
    int er = (int)(excl & 0xffffffffULL);
    int totH = (int)(s_total >> 32);
    int excess = totH > HALF_S ? totH - HALF_S : 0;

    int base = tid * 64;
    int* slots = g_idx + pair*MAXS;
#pragma unroll
    for (int i = 0; i < 16; i++) {
        unsigned labm = __vcmpeq4(w[i] & 0x0F0F0F0Fu, clsL);
        if (!labm) continue;
        unsigned pdm = __vcmpeq4(w[i] & 0xF0F0F0F0u, clsH);
#pragma unroll
        for (int k = 0; k < 4; k++) {
            if ((labm >> (k*8)) & 0xffu) {
                int p = base + i*4 + k;
                if ((pdm >> (k*8)) & 0xffu) {
                    int slot = HALF_S + excess + er;
                    if (slot < MAXS) slots[slot] = p;
                    er++;
                } else {
                    if (hr < MAXS) slots[hr] = p;
                    hr++;
                }
            }
        }
    }
}

// ------------- gather: 4 samples per thread, float4 store (R5 version) ------
__global__ void k_gather(const float* __restrict__ feat, float* __restrict__ out) {
    int t = blockIdx.x * blockDim.x + threadIdx.x;   // over NFEAT/4
    if (t >= NFEAT/4) return;
    int s4   = t & 255;              // sample group (4 samples)
    int c    = (t >> 8) & (Cc - 1);
    int pair = t >> 14;
    int b = pair / 3;
    const int* slots = g_idx + pair*MAXS + s4*4;
    const float* plane = feat + ((size_t)(b*Cc + c)) * Nn;
    int p0 = slots[0], p1 = slots[1], p2 = slots[2], p3 = slots[3];
    float4 r;
    r.x = (p0 >= 0) ? __ldg(plane + p0) : 0.0f;
    r.y = (p1 >= 0) ? __ldg(plane + p1) : 0.0f;
    r.z = (p2 >= 0) ? __ldg(plane + p2) : 0.0f;
    r.w = (p3 >= 0) ? __ldg(plane + p3) : 0.0f;
    ((float4*)out)[t] = r;
}

extern "C" void kernel_launch(void* const* d_in, const int* in_sizes, int n_in,
                              void* d_out, int out_size) {
    const float* feat   = (const float*)d_in[0];  // [4,64,256,256]
    const int*   labels = (const int*)d_in[1];    // [4,256,256]
    const float* preds  = (const float*)d_in[2];  // [4,4,256,256]
    float* out = (float*)d_out;

    k_prep<<<Bb*ROWS_BLK, PREP_T>>>(preds, labels);
    k_select<<<NPAIRS, 1024>>>(out);
    k_gather<<<(NFEAT/4 + 255) / 256, 256>>>(feat, out);
}